// round 3
// baseline (speedup 1.0000x reference)
#include <cuda_runtime.h>
#include <cmath>

// ---------------- problem constants ----------------
#define BS_     2
#define SEQ_    1024
#define DIM_    2048
#define H_      16
#define QRANK_  768
#define KVRANK_ 512
#define QS_     128      // QK_STATIC
#define ROT_    64       // QK_ROT
#define CD_     576      // KVRANK_ + ROT_  (absorbed QK dim)
#define VD_     128      // V_DIM
#define T_      2048     // BS_*SEQ_ tokens
#define QUP_    3072     // H_*(QS_+ROT_)

// ---------------- scratch (static device globals; no allocs) ----------------
__device__ float g_qd   [(size_t)T_ * QRANK_];
__device__ float g_qn   [(size_t)T_ * QRANK_];
__device__ float g_qfull[(size_t)T_ * QUP_];
__device__ float g_kvraw[(size_t)T_ * CD_];
__device__ float g_kfull[(size_t)T_ * CD_];
__device__ float g_qall [(size_t)BS_ * H_ * SEQ_ * CD_];
__device__ float g_scr  [(size_t)BS_ * H_ * SEQ_ * SEQ_];
__device__ float g_ctxc [(size_t)BS_ * H_ * SEQ_ * KVRANK_];
__device__ float g_ctx  [(size_t)T_ * DIM_];

// ---------------- generic batched SGEMM ----------------
// C[M,N] = alpha * A[M,K] x B + bias
//   transB=1: B is [N,K] row-major (x @ W^T form)
//   transB=0: B is [K,N] row-major
// batch z: zo=z/zdiv, zi=z%zdiv; ptr += zo*s?o + zi*s?i
// causal=1: skip blocks entirely above the diagonal (M==N==SEQ tiles)
// klimit=1: K-loop bounded by m0+BM (reads only lower/diag key tiles)
#define BM  128
#define BN  128
#define BKK 8

__global__ __launch_bounds__(256) void sgemm_kernel(
    const float* __restrict__ A, const float* __restrict__ B, float* __restrict__ C,
    const float* __restrict__ bias,
    int M, int N, int K, int lda, int ldb, int ldc,
    long long sAo, long long sAi, long long sBo, long long sBi,
    long long sCo, long long sCi, int zdiv,
    float alpha, int causal, int klimit, int transB)
{
    int z  = blockIdx.z;
    int zo = z / zdiv, zi = z - zo * zdiv;
    A += zo * sAo + zi * sAi;
    B += zo * sBo + zi * sBi;
    C += zo * sCo + zi * sCi;

    int m0 = blockIdx.y * BM, n0 = blockIdx.x * BN;
    if (causal && n0 > m0) return;
    int kmax = klimit ? min(K, m0 + BM) : K;

    __shared__ float As[BKK][BM];
    __shared__ float Bs[BKK][BN];

    int tid = threadIdx.x;
    int tx = tid & 15, ty = tid >> 4;
    int ar = tid >> 1, ak = (tid & 1) << 2;   // transpose-load lanes (A, trans-B)
    int bk = tid >> 5, bn = (tid & 31) << 2;  // direct-load lanes (notrans-B)

    float acc[8][8];
#pragma unroll
    for (int i = 0; i < 8; i++)
#pragma unroll
        for (int j = 0; j < 8; j++) acc[i][j] = 0.f;

    for (int k0 = 0; k0 < kmax; k0 += BKK) {
        float4 av = *(const float4*)(A + (size_t)(m0 + ar) * lda + (k0 + ak));
        As[ak + 0][ar] = av.x; As[ak + 1][ar] = av.y;
        As[ak + 2][ar] = av.z; As[ak + 3][ar] = av.w;

        if (transB) {
            float4 bv = make_float4(0.f, 0.f, 0.f, 0.f);
            int n = n0 + ar;
            if (n < N) bv = *(const float4*)(B + (size_t)n * ldb + (k0 + ak));
            Bs[ak + 0][ar] = bv.x; Bs[ak + 1][ar] = bv.y;
            Bs[ak + 2][ar] = bv.z; Bs[ak + 3][ar] = bv.w;
        } else {
            float4 bv = make_float4(0.f, 0.f, 0.f, 0.f);
            int n = n0 + bn;
            if (n < N) bv = *(const float4*)(B + (size_t)(k0 + bk) * ldb + n);
            *(float4*)&Bs[bk][bn] = bv;
        }
        __syncthreads();

#pragma unroll
        for (int kk = 0; kk < BKK; kk++) {
            float4 a0 = *(const float4*)&As[kk][ty * 8];
            float4 a1 = *(const float4*)&As[kk][ty * 8 + 4];
            float4 b0 = *(const float4*)&Bs[kk][tx * 8];
            float4 b1 = *(const float4*)&Bs[kk][tx * 8 + 4];
            float aa[8] = {a0.x, a0.y, a0.z, a0.w, a1.x, a1.y, a1.z, a1.w};
            float bb[8] = {b0.x, b0.y, b0.z, b0.w, b1.x, b1.y, b1.z, b1.w};
#pragma unroll
            for (int i = 0; i < 8; i++)
#pragma unroll
                for (int j = 0; j < 8; j++)
                    acc[i][j] += aa[i] * bb[j];
        }
        __syncthreads();
    }

#pragma unroll
    for (int i = 0; i < 8; i++) {
        int row = m0 + ty * 8 + i;
#pragma unroll
        for (int j = 0; j < 8; j++) {
            int col = n0 + tx * 8 + j;
            if (col < N) {
                float v = acc[i][j] * alpha;
                if (bias) v += bias[col];
                C[(size_t)row * ldc + col] = v;
            }
        }
    }
}

// ---------------- pointwise / reduction kernels ----------------
__device__ __forceinline__ float block_reduce_sum(float v, float* red) {
    int tid = threadIdx.x;
    for (int o = 16; o; o >>= 1) v += __shfl_xor_sync(0xffffffffu, v, o);
    if ((tid & 31) == 0) red[tid >> 5] = v;
    __syncthreads();
    if (tid < 32) {
        float w = (tid < (int)(blockDim.x >> 5)) ? red[tid] : 0.f;
        for (int o = 16; o; o >>= 1) w += __shfl_xor_sync(0xffffffffu, w, o);
        red[tid] = w;
    }
    __syncthreads();
    float r = red[0];
    __syncthreads();
    return r;
}

__global__ void rmsnorm_kernel(const float* __restrict__ in, float* __restrict__ out,
                               const float* __restrict__ scale, int N)
{
    __shared__ float red[32];
    int r = blockIdx.x;
    const float* pi = in + (size_t)r * N;
    float* po = out + (size_t)r * N;
    float ss = 0.f;
    for (int c = threadIdx.x; c < N; c += blockDim.x) { float v = pi[c]; ss += v * v; }
    ss = block_reduce_sum(ss, red);
    float inv = rsqrtf(ss / (float)N + 1e-6f);
    for (int c = threadIdx.x; c < N; c += blockDim.x) po[c] = pi[c] * inv * scale[c];
}

__device__ __forceinline__ void rope_angle(int s, int j, float* sn, float* cs) {
    int f = j & 31;
    float invf = 1.0f / powf(10000.0f, (float)(2 * f) / 64.0f);  // matches jax table
    float ang = (float)s * invf;
    sincosf(ang, sn, cs);
}

// kv_raw[t][0:512] --rmsnorm--> k_full[t][0:512]; kv_raw[t][512:576] --rope--> k_full[t][512:576]
__global__ void kv_post_kernel(const float* __restrict__ kvraw,
                               const float* __restrict__ kscale,
                               float* __restrict__ kfull)
{
    __shared__ float red[32];
    int t = blockIdx.x;
    const float* pi = kvraw + (size_t)t * CD_;
    float* po = kfull + (size_t)t * CD_;
    float ss = 0.f;
    for (int c = threadIdx.x; c < KVRANK_; c += blockDim.x) { float v = pi[c]; ss += v * v; }
    ss = block_reduce_sum(ss, red);
    float inv = rsqrtf(ss / (float)KVRANK_ + 1e-6f);
    for (int c = threadIdx.x; c < KVRANK_; c += blockDim.x) po[c] = pi[c] * inv * kscale[c];
    if (threadIdx.x < ROT_) {
        int j = threadIdx.x;
        int s = t & (SEQ_ - 1);
        float sn, cs; rope_angle(s, j, &sn, &cs);
        float xv = pi[KVRANK_ + j];
        float hr = (j < 32) ? -pi[KVRANK_ + j + 32] : pi[KVRANK_ + j - 32];
        po[KVRANK_ + j] = xv * cs + hr * sn;
    }
}

// rope(q_rot) -> q_all[(b*H+h)][s][512+j]
__global__ void q_post_kernel(const float* __restrict__ qfull, float* __restrict__ qall)
{
    int t = blockIdx.x;
    int h = threadIdx.x >> 6, j = threadIdx.x & 63;
    int b = t >> 10, s = t & (SEQ_ - 1);
    const float* src = qfull + (size_t)t * QUP_ + h * (QS_ + ROT_) + QS_;
    float xv = src[j];
    float hr = (j < 32) ? -src[j + 32] : src[j - 32];
    float sn, cs; rope_angle(s, j, &sn, &cs);
    qall[((size_t)(b * H_ + h) * SEQ_ + s) * CD_ + KVRANK_ + j] = xv * cs + hr * sn;
}

// causal softmax over row length s+1; zero-fill P up to the 128-tile boundary
__global__ void softmax_kernel(float* __restrict__ scores)
{
    __shared__ float red[32];
    int s = blockIdx.x, bh = blockIdx.y;
    float* row = scores + ((size_t)bh * SEQ_ + s) * SEQ_;
    int L = s + 1;
    int tid = threadIdx.x;

    float m = -1e30f;
    for (int c = tid; c < L; c += blockDim.x) m = fmaxf(m, row[c]);
    for (int o = 16; o; o >>= 1) m = fmaxf(m, __shfl_xor_sync(0xffffffffu, m, o));
    if ((tid & 31) == 0) red[tid >> 5] = m;
    __syncthreads();
    if (tid < 32) {
        float w = (tid < (int)(blockDim.x >> 5)) ? red[tid] : -1e30f;
        for (int o = 16; o; o >>= 1) w = fmaxf(w, __shfl_xor_sync(0xffffffffu, w, o));
        red[tid] = w;
    }
    __syncthreads();
    m = red[0];
    __syncthreads();

    float sum = 0.f;
    for (int c = tid; c < L; c += blockDim.x) {
        float e = expf(row[c] - m);
        row[c] = e;
        sum += e;
    }
    sum = block_reduce_sum(sum, red);
    float inv = 1.f / sum;
    for (int c = tid; c < L; c += blockDim.x) row[c] *= inv;

    int end = ((s >> 7) + 1) << 7;   // tile boundary the P*V GEMM reads up to
    for (int c = L + tid; c < end; c += blockDim.x) row[c] = 0.f;
}

// ---------------- host side ----------------
static void launch_gemm(const float* A, const float* B, float* C, const float* bias,
                        int M, int N, int K, int lda, int ldb, int ldc,
                        long long sAo, long long sAi, long long sBo, long long sBi,
                        long long sCo, long long sCi, int zdiv, int nbatch,
                        float alpha, int causal, int klimit, int transB)
{
    dim3 grid((N + BN - 1) / BN, M / BM, nbatch);
    sgemm_kernel<<<grid, 256>>>(A, B, C, bias, M, N, K, lda, ldb, ldc,
                                sAo, sAi, sBo, sBi, sCo, sCi, zdiv,
                                alpha, causal, klimit, transB);
}

extern "C" void kernel_launch(void* const* d_in, const int* in_sizes, int n_in,
                              void* d_out, int out_size)
{
    const float* x   = (const float*)d_in[0];
    // d_in[1] = start_pos (ignored by reference), d_in[2] = mask (pure causal, applied analytically)
    const float* qdw = (const float*)d_in[3];
    const float* qdb = (const float*)d_in[4];
    const float* qns = (const float*)d_in[5];
    const float* quw = (const float*)d_in[6];
    const float* qub = (const float*)d_in[7];
    const float* kdw = (const float*)d_in[8];
    const float* kdb = (const float*)d_in[9];
    const float* kns = (const float*)d_in[10];
    const float* kuw = (const float*)d_in[11];
    const float* ow  = (const float*)d_in[12];
    const float* ob  = (const float*)d_in[13];
    float* out = (float*)d_out;

    float *qd, *qn, *qfull, *kvraw, *kfull, *qall, *scores, *ctxc, *ctx;
    cudaGetSymbolAddress((void**)&qd,     g_qd);
    cudaGetSymbolAddress((void**)&qn,     g_qn);
    cudaGetSymbolAddress((void**)&qfull,  g_qfull);
    cudaGetSymbolAddress((void**)&kvraw,  g_kvraw);
    cudaGetSymbolAddress((void**)&kfull,  g_kfull);
    cudaGetSymbolAddress((void**)&qall,   g_qall);
    cudaGetSymbolAddress((void**)&scores, g_scr);
    cudaGetSymbolAddress((void**)&ctxc,   g_ctxc);
    cudaGetSymbolAddress((void**)&ctx,    g_ctx);

    const float inv_sqrt_d = 1.0f / sqrtf(192.0f);

    // 1) q_down: [T,2048] @ W[768,2048]^T + b
    launch_gemm(x, qdw, qd, qdb, T_, QRANK_, DIM_, DIM_, DIM_, QRANK_,
                0, 0, 0, 0, 0, 0, 1, 1, 1.f, 0, 0, 1);
    rmsnorm_kernel<<<T_, 256>>>(qd, qn, qns, QRANK_);

    // 2) q_up: [T,768] @ W[3072,768]^T + b
    launch_gemm(qn, quw, qfull, qub, T_, QUP_, QRANK_, QRANK_, QRANK_, QUP_,
                0, 0, 0, 0, 0, 0, 1, 1, 1.f, 0, 0, 1);

    // 3) kv_down: [T,2048] @ W[576,2048]^T + b  (N=576 handled by N-guards)
    launch_gemm(x, kdw, kvraw, kdb, T_, CD_, DIM_, DIM_, DIM_, CD_,
                0, 0, 0, 0, 0, 0, 1, 1, 1.f, 0, 0, 1);
    kv_post_kernel<<<T_, 256>>>(kvraw, kns, kfull);
    q_post_kernel<<<T_, 1024>>>(qfull, qall);

    // 4) absorbed q: per (b,h): q_static[1024,128] @ w_k[h][128,512] -> q_all[...,0:512]
    launch_gemm(qfull, kuw, qall, nullptr, SEQ_, KVRANK_, QS_,
                QUP_, KVRANK_, CD_,
                (long long)SEQ_ * QUP_, (long long)(QS_ + ROT_),
                0, (long long)QS_ * KVRANK_,
                (long long)H_ * SEQ_ * CD_, (long long)SEQ_ * CD_,
                H_, BS_ * H_, 1.f, 0, 0, 0);

    // 5) scores: per (b,h): Q[1024,576] @ K[1024,576]^T / sqrt(192), causal tile-skip
    launch_gemm(qall, kfull, scores, nullptr, SEQ_, SEQ_, CD_,
                CD_, CD_, SEQ_,
                (long long)H_ * SEQ_ * CD_, (long long)SEQ_ * CD_,
                (long long)SEQ_ * CD_, 0,
                (long long)H_ * SEQ_ * SEQ_, (long long)SEQ_ * SEQ_,
                H_, BS_ * H_, inv_sqrt_d, 1, 0, 1);

    softmax_kernel<<<dim3(SEQ_, BS_ * H_), 256>>>(scores);

    // 6) ctx_c: per (b,h): P[1024,1024] @ V[1024,512] with causal K-limit
    launch_gemm(scores, kfull, ctxc, nullptr, SEQ_, KVRANK_, SEQ_,
                SEQ_, CD_, KVRANK_,
                (long long)H_ * SEQ_ * SEQ_, (long long)SEQ_ * SEQ_,
                (long long)SEQ_ * CD_, 0,
                (long long)H_ * SEQ_ * KVRANK_, (long long)SEQ_ * KVRANK_,
                H_, BS_ * H_, 1.f, 0, 1, 0);

    // 7) v-proj: per (b,h): ctx_c[1024,512] @ w_v[h][128,512]^T -> ctx[b*S+s][h*128+d]
    launch_gemm(ctxc, kuw + (size_t)H_ * QS_ * KVRANK_, ctx, nullptr, SEQ_, VD_, KVRANK_,
                KVRANK_, KVRANK_, DIM_,
                (long long)H_ * SEQ_ * KVRANK_, (long long)SEQ_ * KVRANK_,
                0, (long long)VD_ * KVRANK_,
                (long long)SEQ_ * DIM_, (long long)VD_,
                H_, BS_ * H_, 1.f, 0, 0, 1);

    // 8) out: [T,2048] @ W[2048,2048]^T + b
    launch_gemm(ctx, ow, out, ob, T_, DIM_, DIM_, DIM_, DIM_, DIM_,
                0, 0, 0, 0, 0, 0, 1, 1, 1.f, 0, 0, 1);
}

// round 8
// speedup vs baseline: 2.3942x; 2.3942x over previous
#include <cuda_runtime.h>
#include <cuda_bf16.h>
#include <cstdint>
#include <cmath>

// ---------------- problem constants ----------------
#define BS_     2
#define SEQ_    1024
#define DIM_    2048
#define H_      16
#define QRANK_  768
#define KVRANK_ 512
#define QS_     128
#define ROT_    64
#define CD_     576
#define VD_     128
#define T_      2048
#define QUP_    3072

// ---------------- scratch ----------------
__device__ float g_qd   [(size_t)T_ * QRANK_];
__device__ float g_qn   [(size_t)T_ * QRANK_];
__device__ float g_qfull[(size_t)T_ * QUP_];
__device__ float g_kvraw[(size_t)T_ * CD_];
__device__ float g_kfull[(size_t)T_ * CD_];
__device__ float g_qall [(size_t)BS_ * H_ * SEQ_ * CD_];
__device__ float g_scr  [(size_t)BS_ * H_ * SEQ_ * SEQ_];
__device__ float g_ctxc [(size_t)BS_ * H_ * SEQ_ * KVRANK_];
__device__ float g_ctx  [(size_t)T_ * DIM_];

// ---------------- helpers ----------------
__device__ __forceinline__ uint32_t smem_u32(const void* p) {
    uint32_t a;
    asm("{ .reg .u64 t; cvta.to.shared.u64 t, %1; cvt.u32.u64 %0, t; }" : "=r"(a) : "l"(p));
    return a;
}

__device__ __forceinline__ void ldsm4(uint32_t* r, uint32_t addr) {
    asm volatile("ldmatrix.sync.aligned.m8n8.x4.shared.b16 {%0,%1,%2,%3}, [%4];"
        : "=r"(r[0]), "=r"(r[1]), "=r"(r[2]), "=r"(r[3]) : "r"(addr));
}

__device__ __forceinline__ void mma16816(float* c, const uint32_t* a, const uint32_t* b) {
    asm volatile("mma.sync.aligned.m16n8k16.row.col.f32.bf16.bf16.f32 "
        "{%0,%1,%2,%3}, {%4,%5,%6,%7}, {%8,%9}, {%0,%1,%2,%3};"
        : "+f"(c[0]), "+f"(c[1]), "+f"(c[2]), "+f"(c[3])
        : "r"(a[0]), "r"(a[1]), "r"(a[2]), "r"(a[3]), "r"(b[0]), "r"(b[1]));
}

__device__ __forceinline__ void split4(float4 v, uint64_t& hi, uint64_t& lo) {
    __nv_bfloat16 h0 = __float2bfloat16(v.x), h1 = __float2bfloat16(v.y);
    __nv_bfloat16 h2 = __float2bfloat16(v.z), h3 = __float2bfloat16(v.w);
    __nv_bfloat16 l0 = __float2bfloat16(v.x - __bfloat162float(h0));
    __nv_bfloat16 l1 = __float2bfloat16(v.y - __bfloat162float(h1));
    __nv_bfloat16 l2 = __float2bfloat16(v.z - __bfloat162float(h2));
    __nv_bfloat16 l3 = __float2bfloat16(v.w - __bfloat162float(h3));
    hi = (uint64_t)__bfloat16_as_ushort(h0) | ((uint64_t)__bfloat16_as_ushort(h1) << 16)
       | ((uint64_t)__bfloat16_as_ushort(h2) << 32) | ((uint64_t)__bfloat16_as_ushort(h3) << 48);
    lo = (uint64_t)__bfloat16_as_ushort(l0) | ((uint64_t)__bfloat16_as_ushort(l1) << 16)
       | ((uint64_t)__bfloat16_as_ushort(l2) << 32) | ((uint64_t)__bfloat16_as_ushort(l3) << 48);
}
__device__ __forceinline__ void split1(float v, __nv_bfloat16& h, __nv_bfloat16& l) {
    h = __float2bfloat16(v);
    l = __float2bfloat16(v - __bfloat162float(h));
}

// ---------------- smem layout ----------------
#define KC      64
#define SA      72                         // bf16 elements per smem row (64 + 8 pad)
#define TILE_B  (128 * SA * 2)             // 18432 bytes
#define SM_AHI  0
#define SM_ALO  (TILE_B)
#define SM_BHI  (2 * TILE_B)
#define SM_BLO  (3 * TILE_B)
#define SMEM_TOTAL (4 * TILE_B)            // 73728; staging (67584) overlaps at offset 0
#define CS_LD   132

// ---------------- mma.sync batched GEMM ----------------
// C[M,N] = alpha * A[M,K] x op(B) + bias  (same contract as before)
__global__ __launch_bounds__(256, 2) void gemm_tc(
    const float* __restrict__ A, const float* __restrict__ B, float* __restrict__ C,
    const float* __restrict__ bias,
    int M, int N, int K, int lda, int ldb, int ldc,
    long long sAo, long long sAi, long long sBo, long long sBi,
    long long sCo, long long sCi, int zdiv,
    float alpha, int causal, int klimit, int transB)
{
    int z = blockIdx.z;
    int zo = z / zdiv, zi = z - zo * zdiv;
    A += zo * sAo + zi * sAi;
    B += zo * sBo + zi * sBi;
    C += zo * sCo + zi * sCi;

    int m0 = blockIdx.y * 128, n0 = blockIdx.x * 128;
    if (causal && n0 > m0) return;
    int kmax = klimit ? min(K, m0 + 128) : K;
    int nchunks = kmax / KC;

    extern __shared__ char smem[];
    uint32_t sb = smem_u32(smem);
    int tid = threadIdx.x, wid = tid >> 5, lane = tid & 31;
    int wm = wid & 1, wn = wid >> 1;       // warp tile: 64(M) x 32(N)

    float acc[4][4][4];
#pragma unroll
    for (int i = 0; i < 4; i++)
#pragma unroll
        for (int j = 0; j < 4; j++)
#pragma unroll
            for (int q = 0; q < 4; q++) acc[i][j][q] = 0.f;

    // per-lane ldmatrix offsets (elements)
    int a_loff = (lane & 15) * SA + ((lane >> 4) << 3);
    int b_loff = ((lane & 7) + ((lane & 16) >> 1)) * SA + (lane & 8);
    uint32_t aHi = sb + SM_AHI + 2u * ((uint32_t)(wm * 64) * SA + a_loff);
    uint32_t aLo = sb + SM_ALO + 2u * ((uint32_t)(wm * 64) * SA + a_loff);
    uint32_t bHi = sb + SM_BHI + 2u * ((uint32_t)(wn * 32) * SA + b_loff);
    uint32_t bLo = sb + SM_BLO + 2u * ((uint32_t)(wn * 32) * SA + b_loff);

    for (int ch = 0; ch < nchunks; ch++) {
        int k0 = ch * KC;
        if (ch) __syncthreads();

        // ---- A tile: 128 x 64 fp32 -> hi/lo bf16 [m][k] ----
        {
            int r0 = tid >> 4, kq = (tid & 15) << 2;
            const float* Ap = A + (size_t)m0 * lda + k0 + kq;
#pragma unroll
            for (int i = 0; i < 8; i++) {
                int r = r0 + i * 16;
                float4 v = *(const float4*)(Ap + (size_t)r * lda);
                uint64_t hv, lv; split4(v, hv, lv);
                uint32_t off = 2u * (uint32_t)(r * SA + kq);
                *(uint64_t*)(smem + SM_AHI + off) = hv;
                *(uint64_t*)(smem + SM_ALO + off) = lv;
            }
        }
        // ---- B tile: 128(N) x 64(K) -> hi/lo bf16 [n][k] ----
        if (transB) {
            int r0 = tid >> 4, kq = (tid & 15) << 2;
#pragma unroll
            for (int i = 0; i < 8; i++) {
                int r = r0 + i * 16;
                float4 v = make_float4(0.f, 0.f, 0.f, 0.f);
                if (n0 + r < N) v = *(const float4*)(B + (size_t)(n0 + r) * ldb + k0 + kq);
                uint64_t hv, lv; split4(v, hv, lv);
                uint32_t off = 2u * (uint32_t)(r * SA + kq);
                *(uint64_t*)(smem + SM_BHI + off) = hv;
                *(uint64_t*)(smem + SM_BLO + off) = lv;
            }
        } else {
            int kk0 = tid >> 5, nq = (tid & 31) << 2;
#pragma unroll
            for (int i = 0; i < 8; i++) {
                int k = kk0 + i * 8;
                float4 v = make_float4(0.f, 0.f, 0.f, 0.f);
                if (n0 + nq < N) v = *(const float4*)(B + (size_t)(k0 + k) * ldb + n0 + nq);
                float vv[4] = {v.x, v.y, v.z, v.w};
#pragma unroll
                for (int j = 0; j < 4; j++) {
                    __nv_bfloat16 h, l; split1(vv[j], h, l);
                    uint32_t off = 2u * (uint32_t)((nq + j) * SA + k);
                    *(__nv_bfloat16*)(smem + SM_BHI + off) = h;
                    *(__nv_bfloat16*)(smem + SM_BLO + off) = l;
                }
            }
        }
        __syncthreads();

        // ---- MMA: 4 k16 steps, 3 split passes ----
#pragma unroll
        for (int ks = 0; ks < 4; ks++) {
            uint32_t koff = 2u * (uint32_t)(ks * 16);
            uint32_t bh[2][4], bl[2][4], af[4][4];
#pragma unroll
            for (int jj = 0; jj < 2; jj++) {
                ldsm4(bh[jj], bHi + 2u * (uint32_t)(jj * 16 * SA) + koff);
                ldsm4(bl[jj], bLo + 2u * (uint32_t)(jj * 16 * SA) + koff);
            }
#pragma unroll
            for (int i = 0; i < 4; i++)
                ldsm4(af[i], aHi + 2u * (uint32_t)(i * 16 * SA) + koff);
#pragma unroll
            for (int i = 0; i < 4; i++)
#pragma unroll
                for (int j = 0; j < 4; j++) {
                    mma16816(acc[i][j], af[i], &bh[j >> 1][(j & 1) * 2]);
                    mma16816(acc[i][j], af[i], &bl[j >> 1][(j & 1) * 2]);
                }
#pragma unroll
            for (int i = 0; i < 4; i++)
                ldsm4(af[i], aLo + 2u * (uint32_t)(i * 16 * SA) + koff);
#pragma unroll
            for (int i = 0; i < 4; i++)
#pragma unroll
                for (int j = 0; j < 4; j++)
                    mma16816(acc[i][j], af[i], &bh[j >> 1][(j & 1) * 2]);
        }
    }

    // ---- epilogue: regs -> smem staging -> coalesced gmem ----
    __syncthreads();
    {
        float* Cs = (float*)smem;
        int g = lane >> 2, t = lane & 3;
#pragma unroll
        for (int i = 0; i < 4; i++)
#pragma unroll
            for (int j = 0; j < 4; j++) {
                int r = wm * 64 + i * 16 + g;
                int c = wn * 32 + j * 8 + t * 2;
                *(float2*)&Cs[r * CS_LD + c]       = make_float2(acc[i][j][0], acc[i][j][1]);
                *(float2*)&Cs[(r + 8) * CS_LD + c] = make_float2(acc[i][j][2], acc[i][j][3]);
            }
    }
    __syncthreads();
    {
        const float* Cs = (const float*)smem;
        int c4 = lane << 2;
#pragma unroll
        for (int i = 0; i < 16; i++) {
            int r = i * 8 + (tid >> 5);
            if (n0 + c4 < N) {
                float4 v = *(const float4*)&Cs[r * CS_LD + c4];
                v.x *= alpha; v.y *= alpha; v.z *= alpha; v.w *= alpha;
                if (bias) {
                    float4 bv = *(const float4*)(bias + n0 + c4);
                    v.x += bv.x; v.y += bv.y; v.z += bv.z; v.w += bv.w;
                }
                *(float4*)(C + (size_t)(m0 + r) * ldc + n0 + c4) = v;
            }
        }
    }
}

// ---------------- pointwise kernels (unchanged from passing R3) ----------------
__device__ __forceinline__ float block_reduce_sum(float v, float* red) {
    int tid = threadIdx.x;
    for (int o = 16; o; o >>= 1) v += __shfl_xor_sync(0xffffffffu, v, o);
    if ((tid & 31) == 0) red[tid >> 5] = v;
    __syncthreads();
    if (tid < 32) {
        float w = (tid < (int)(blockDim.x >> 5)) ? red[tid] : 0.f;
        for (int o = 16; o; o >>= 1) w += __shfl_xor_sync(0xffffffffu, w, o);
        red[tid] = w;
    }
    __syncthreads();
    float r = red[0];
    __syncthreads();
    return r;
}

__global__ void rmsnorm_kernel(const float* __restrict__ in, float* __restrict__ out,
                               const float* __restrict__ scale, int N)
{
    __shared__ float red[32];
    int r = blockIdx.x;
    const float* pi = in + (size_t)r * N;
    float* po = out + (size_t)r * N;
    float ss = 0.f;
    for (int c = threadIdx.x; c < N; c += blockDim.x) { float v = pi[c]; ss += v * v; }
    ss = block_reduce_sum(ss, red);
    float inv = rsqrtf(ss / (float)N + 1e-6f);
    for (int c = threadIdx.x; c < N; c += blockDim.x) po[c] = pi[c] * inv * scale[c];
}

__device__ __forceinline__ void rope_angle(int s, int j, float* sn, float* cs) {
    int f = j & 31;
    float invf = 1.0f / powf(10000.0f, (float)(2 * f) / 64.0f);
    float ang = (float)s * invf;
    sincosf(ang, sn, cs);
}

__global__ void kv_post_kernel(const float* __restrict__ kvraw,
                               const float* __restrict__ kscale,
                               float* __restrict__ kfull)
{
    __shared__ float red[32];
    int t = blockIdx.x;
    const float* pi = kvraw + (size_t)t * CD_;
    float* po = kfull + (size_t)t * CD_;
    float ss = 0.f;
    for (int c = threadIdx.x; c < KVRANK_; c += blockDim.x) { float v = pi[c]; ss += v * v; }
    ss = block_reduce_sum(ss, red);
    float inv = rsqrtf(ss / (float)KVRANK_ + 1e-6f);
    for (int c = threadIdx.x; c < KVRANK_; c += blockDim.x) po[c] = pi[c] * inv * kscale[c];
    if (threadIdx.x < ROT_) {
        int j = threadIdx.x;
        int s = t & (SEQ_ - 1);
        float sn, cs; rope_angle(s, j, &sn, &cs);
        float xv = pi[KVRANK_ + j];
        float hr = (j < 32) ? -pi[KVRANK_ + j + 32] : pi[KVRANK_ + j - 32];
        po[KVRANK_ + j] = xv * cs + hr * sn;
    }
}

__global__ void q_post_kernel(const float* __restrict__ qfull, float* __restrict__ qall)
{
    int t = blockIdx.x;
    int h = threadIdx.x >> 6, j = threadIdx.x & 63;
    int b = t >> 10, s = t & (SEQ_ - 1);
    const float* src = qfull + (size_t)t * QUP_ + h * (QS_ + ROT_) + QS_;
    float xv = src[j];
    float hr = (j < 32) ? -src[j + 32] : src[j - 32];
    float sn, cs; rope_angle(s, j, &sn, &cs);
    qall[((size_t)(b * H_ + h) * SEQ_ + s) * CD_ + KVRANK_ + j] = xv * cs + hr * sn;
}

__global__ void softmax_kernel(float* __restrict__ scores)
{
    __shared__ float red[32];
    int s = blockIdx.x, bh = blockIdx.y;
    float* row = scores + ((size_t)bh * SEQ_ + s) * SEQ_;
    int L = s + 1;
    int tid = threadIdx.x;

    float m = -1e30f;
    for (int c = tid; c < L; c += blockDim.x) m = fmaxf(m, row[c]);
    for (int o = 16; o; o >>= 1) m = fmaxf(m, __shfl_xor_sync(0xffffffffu, m, o));
    if ((tid & 31) == 0) red[tid >> 5] = m;
    __syncthreads();
    if (tid < 32) {
        float w = (tid < (int)(blockDim.x >> 5)) ? red[tid] : -1e30f;
        for (int o = 16; o; o >>= 1) w = fmaxf(w, __shfl_xor_sync(0xffffffffu, w, o));
        red[tid] = w;
    }
    __syncthreads();
    m = red[0];
    __syncthreads();

    float sum = 0.f;
    for (int c = tid; c < L; c += blockDim.x) {
        float e = expf(row[c] - m);
        row[c] = e;
        sum += e;
    }
    sum = block_reduce_sum(sum, red);
    float inv = 1.f / sum;
    for (int c = tid; c < L; c += blockDim.x) row[c] *= inv;

    int end = ((s >> 7) + 1) << 7;
    for (int c = L + tid; c < end; c += blockDim.x) row[c] = 0.f;
}

// ---------------- host side ----------------
static void launch_gemm(const float* A, const float* B, float* C, const float* bias,
                        int M, int N, int K, int lda, int ldb, int ldc,
                        long long sAo, long long sAi, long long sBo, long long sBi,
                        long long sCo, long long sCi, int zdiv, int nbatch,
                        float alpha, int causal, int klimit, int transB)
{
    dim3 grid((N + 127) / 128, M / 128, nbatch);
    gemm_tc<<<grid, 256, SMEM_TOTAL>>>(A, B, C, bias, M, N, K, lda, ldb, ldc,
                                       sAo, sAi, sBo, sBi, sCo, sCi, zdiv,
                                       alpha, causal, klimit, transB);
}

extern "C" void kernel_launch(void* const* d_in, const int* in_sizes, int n_in,
                              void* d_out, int out_size)
{
    const float* x   = (const float*)d_in[0];
    const float* qdw = (const float*)d_in[3];
    const float* qdb = (const float*)d_in[4];
    const float* qns = (const float*)d_in[5];
    const float* quw = (const float*)d_in[6];
    const float* qub = (const float*)d_in[7];
    const float* kdw = (const float*)d_in[8];
    const float* kdb = (const float*)d_in[9];
    const float* kns = (const float*)d_in[10];
    const float* kuw = (const float*)d_in[11];
    const float* ow  = (const float*)d_in[12];
    const float* ob  = (const float*)d_in[13];
    float* out = (float*)d_out;

    cudaFuncSetAttribute(gemm_tc, cudaFuncAttributeMaxDynamicSharedMemorySize, SMEM_TOTAL);

    float *qd, *qn, *qfull, *kvraw, *kfull, *qall, *scores, *ctxc, *ctx;
    cudaGetSymbolAddress((void**)&qd,     g_qd);
    cudaGetSymbolAddress((void**)&qn,     g_qn);
    cudaGetSymbolAddress((void**)&qfull,  g_qfull);
    cudaGetSymbolAddress((void**)&kvraw,  g_kvraw);
    cudaGetSymbolAddress((void**)&kfull,  g_kfull);
    cudaGetSymbolAddress((void**)&qall,   g_qall);
    cudaGetSymbolAddress((void**)&scores, g_scr);
    cudaGetSymbolAddress((void**)&ctxc,   g_ctxc);
    cudaGetSymbolAddress((void**)&ctx,    g_ctx);

    const float inv_sqrt_d = 1.0f / sqrtf(192.0f);

    // 1) q_down
    launch_gemm(x, qdw, qd, qdb, T_, QRANK_, DIM_, DIM_, DIM_, QRANK_,
                0, 0, 0, 0, 0, 0, 1, 1, 1.f, 0, 0, 1);
    rmsnorm_kernel<<<T_, 256>>>(qd, qn, qns, QRANK_);

    // 2) q_up
    launch_gemm(qn, quw, qfull, qub, T_, QUP_, QRANK_, QRANK_, QRANK_, QUP_,
                0, 0, 0, 0, 0, 0, 1, 1, 1.f, 0, 0, 1);

    // 3) kv_down
    launch_gemm(x, kdw, kvraw, kdb, T_, CD_, DIM_, DIM_, DIM_, CD_,
                0, 0, 0, 0, 0, 0, 1, 1, 1.f, 0, 0, 1);
    kv_post_kernel<<<T_, 256>>>(kvraw, kns, kfull);
    q_post_kernel<<<T_, 1024>>>(qfull, qall);

    // 4) absorbed q
    launch_gemm(qfull, kuw, qall, nullptr, SEQ_, KVRANK_, QS_,
                QUP_, KVRANK_, CD_,
                (long long)SEQ_ * QUP_, (long long)(QS_ + ROT_),
                0, (long long)QS_ * KVRANK_,
                (long long)H_ * SEQ_ * CD_, (long long)SEQ_ * CD_,
                H_, BS_ * H_, 1.f, 0, 0, 0);

    // 5) scores (causal tile-skip)
    launch_gemm(qall, kfull, scores, nullptr, SEQ_, SEQ_, CD_,
                CD_, CD_, SEQ_,
                (long long)H_ * SEQ_ * CD_, (long long)SEQ_ * CD_,
                (long long)SEQ_ * CD_, 0,
                (long long)H_ * SEQ_ * SEQ_, (long long)SEQ_ * SEQ_,
                H_, BS_ * H_, inv_sqrt_d, 1, 0, 1);

    softmax_kernel<<<dim3(SEQ_, BS_ * H_), 256>>>(scores);

    // 6) ctx_c (causal K-limit)
    launch_gemm(scores, kfull, ctxc, nullptr, SEQ_, KVRANK_, SEQ_,
                SEQ_, CD_, KVRANK_,
                (long long)H_ * SEQ_ * SEQ_, (long long)SEQ_ * SEQ_,
                (long long)SEQ_ * CD_, 0,
                (long long)H_ * SEQ_ * KVRANK_, (long long)SEQ_ * KVRANK_,
                H_, BS_ * H_, 1.f, 0, 1, 0);

    // 7) v-proj
    launch_gemm(ctxc, kuw + (size_t)H_ * QS_ * KVRANK_, ctx, nullptr, SEQ_, VD_, KVRANK_,
                KVRANK_, KVRANK_, DIM_,
                (long long)H_ * SEQ_ * KVRANK_, (long long)SEQ_ * KVRANK_,
                0, (long long)VD_ * KVRANK_,
                (long long)SEQ_ * DIM_, (long long)VD_,
                H_, BS_ * H_, 1.f, 0, 0, 1);

    // 8) out
    launch_gemm(ctx, ow, out, ob, T_, DIM_, DIM_, DIM_, DIM_, DIM_,
                0, 0, 0, 0, 0, 0, 1, 1, 1.f, 0, 0, 1);
}

// round 10
// speedup vs baseline: 2.9791x; 1.2443x over previous
#include <cuda_runtime.h>
#include <cuda_bf16.h>
#include <cstdint>
#include <cmath>

// ---------------- problem constants ----------------
#define BS_     2
#define SEQ_    1024
#define DIM_    2048
#define H_      16
#define QRANK_  768
#define KVRANK_ 512
#define QS_     128
#define ROT_    64
#define CD_     576
#define VD_     128
#define T_      2048
#define QUP_    3072

typedef unsigned short u16;

// ---------------- fp32 scratch ----------------
__device__ float g_qd   [(size_t)T_ * QRANK_];
__device__ float g_kvraw[(size_t)T_ * CD_];
__device__ float g_qfull[(size_t)T_ * QUP_];
__device__ float g_scr  [(size_t)BS_ * H_ * SEQ_ * SEQ_];

// ---------------- bf16 hi/lo scratch ----------------
#define DECL2(name, n) __device__ __align__(16) u16 name##h[(size_t)(n)]; \
                       __device__ __align__(16) u16 name##l[(size_t)(n)];
DECL2(s_x,    T_ * DIM_)
DECL2(s_qdw,  QRANK_ * DIM_)
DECL2(s_quw,  QUP_ * QRANK_)
DECL2(s_kdw,  CD_ * DIM_)
DECL2(s_ow,   DIM_ * DIM_)
DECL2(s_kKT,  H_ * KVRANK_ * QS_)     // transposed w_k: [h][c][d]
DECL2(s_kV,   H_ * VD_ * KVRANK_)
DECL2(s_qn,   T_ * QRANK_)
DECL2(s_qf,   T_ * QUP_)
DECL2(s_kf,   T_ * CD_)
DECL2(s_kfT,  BS_ * KVRANK_ * SEQ_)   // [b][c][t]
DECL2(s_qa,   (size_t)BS_ * H_ * SEQ_ * CD_)
DECL2(s_P,    (size_t)BS_ * H_ * SEQ_ * SEQ_)
DECL2(s_cc,   (size_t)BS_ * H_ * SEQ_ * KVRANK_)
DECL2(s_cx,   T_ * DIM_)

// ---------------- helpers ----------------
__device__ __forceinline__ uint32_t smem_u32(const void* p) {
    uint32_t a;
    asm("{ .reg .u64 t; cvta.to.shared.u64 t, %1; cvt.u32.u64 %0, t; }" : "=r"(a) : "l"(p));
    return a;
}
__device__ __forceinline__ void ldsm4(uint32_t* r, uint32_t addr) {
    asm volatile("ldmatrix.sync.aligned.m8n8.x4.shared.b16 {%0,%1,%2,%3}, [%4];"
        : "=r"(r[0]), "=r"(r[1]), "=r"(r[2]), "=r"(r[3]) : "r"(addr));
}
__device__ __forceinline__ void mma16816(float* c, const uint32_t* a, const uint32_t* b) {
    asm volatile("mma.sync.aligned.m16n8k16.row.col.f32.bf16.bf16.f32 "
        "{%0,%1,%2,%3}, {%4,%5,%6,%7}, {%8,%9}, {%0,%1,%2,%3};"
        : "+f"(c[0]), "+f"(c[1]), "+f"(c[2]), "+f"(c[3])
        : "r"(a[0]), "r"(a[1]), "r"(a[2]), "r"(a[3]), "r"(b[0]), "r"(b[1]));
}
__device__ __forceinline__ void cpa16(uint32_t dst, const void* src, int sz) {
    asm volatile("cp.async.cg.shared.global [%0], [%1], 16, %2;"
        :: "r"(dst), "l"(src), "r"(sz) : "memory");
}
#define CP_COMMIT() asm volatile("cp.async.commit_group;" ::: "memory")
#define CP_WAIT1()  asm volatile("cp.async.wait_group 1;" ::: "memory")

__device__ __forceinline__ void split4(float4 v, uint64_t& hi, uint64_t& lo) {
    __nv_bfloat16 h0 = __float2bfloat16(v.x), h1 = __float2bfloat16(v.y);
    __nv_bfloat16 h2 = __float2bfloat16(v.z), h3 = __float2bfloat16(v.w);
    __nv_bfloat16 l0 = __float2bfloat16(v.x - __bfloat162float(h0));
    __nv_bfloat16 l1 = __float2bfloat16(v.y - __bfloat162float(h1));
    __nv_bfloat16 l2 = __float2bfloat16(v.z - __bfloat162float(h2));
    __nv_bfloat16 l3 = __float2bfloat16(v.w - __bfloat162float(h3));
    hi = (uint64_t)__bfloat16_as_ushort(h0) | ((uint64_t)__bfloat16_as_ushort(h1) << 16)
       | ((uint64_t)__bfloat16_as_ushort(h2) << 32) | ((uint64_t)__bfloat16_as_ushort(h3) << 48);
    lo = (uint64_t)__bfloat16_as_ushort(l0) | ((uint64_t)__bfloat16_as_ushort(l1) << 16)
       | ((uint64_t)__bfloat16_as_ushort(l2) << 32) | ((uint64_t)__bfloat16_as_ushort(l3) << 48);
}
__device__ __forceinline__ void split1(float v, u16& h, u16& l) {
    __nv_bfloat16 hb = __float2bfloat16(v);
    h = __bfloat16_as_ushort(hb);
    l = __bfloat16_as_ushort(__float2bfloat16(v - __bfloat162float(hb)));
}

// ---------------- smem layout ----------------
#define KC      32
#define SP      40                     // bf16 elems/row (32 + 8 pad); 80B, 16B-aligned
#define TILE_B  (128 * SP * 2)         // 10240
#define OFF_AH  0
#define OFF_AL  (TILE_B)
#define OFF_BH  (2 * TILE_B)
#define OFF_BL  (3 * TILE_B)
#define STAGE_B (4 * TILE_B)           // 40960
#define SMEM_TOTAL (2 * STAGE_B)       // 81920; staging (128*132*4=67584) overlaps
#define CS_LD   132

// ---------------- pipelined bf16 GEMM ----------------
// C = alpha * A x B^T + bias ; A:[M,K] hi/lo, B:[N,K] hi/lo (both k-contiguous)
__global__ __launch_bounds__(256, 2) void gemm_bf(
    const u16* __restrict__ Ah, const u16* __restrict__ Al,
    const u16* __restrict__ Bh, const u16* __restrict__ Bl,
    float* __restrict__ Cf, u16* __restrict__ Ch, u16* __restrict__ Cl,
    const float* __restrict__ bias,
    int M, int N, int K, int lda, int ldb, int ldc,
    long long sAo, long long sAi, long long sBo, long long sBi,
    long long sCo, long long sCi, int zdiv,
    float alpha, int causal, int klimit)
{
    int z = blockIdx.z;
    int zo = z / zdiv, zi = z - zo * zdiv;
    Ah += zo * sAo + zi * sAi;  Al += zo * sAo + zi * sAi;
    Bh += zo * sBo + zi * sBi;  Bl += zo * sBo + zi * sBi;
    long long co = zo * sCo + zi * sCi;
    if (Cf) Cf += co;
    if (Ch) { Ch += co; Cl += co; }

    int m0 = blockIdx.y * 128, n0 = blockIdx.x * 128;
    if (causal && n0 > m0) return;
    int kmax = klimit ? min(K, m0 + 128) : K;
    int nch = kmax / KC;

    extern __shared__ char smem[];
    uint32_t sb = smem_u32(smem);
    int tid = threadIdx.x, wid = tid >> 5, lane = tid & 31;
    int wm = wid & 1, wn = wid >> 1;

    float acc[4][4][4];
#pragma unroll
    for (int i = 0; i < 4; i++)
#pragma unroll
        for (int j = 0; j < 4; j++)
#pragma unroll
            for (int q = 0; q < 4; q++) acc[i][j][q] = 0.f;

    int a_loff = (lane & 15) * SP + ((lane >> 4) << 3);
    int b_loff = ((lane & 7) + ((lane & 16) >> 1)) * SP + (lane & 8);

    // per-thread cp.async lanes: 2 consecutive 16B chunks of one row per tile
    int crow = tid >> 1, cj = (tid & 1) << 1;          // cj in {0,2}
    uint32_t drow = (uint32_t)(crow * 80 + cj * 16);
    int bvalid = (n0 + crow < N) ? 16 : 0;

#define ISSUE(ch_, stb_) do {                                                          \
    int k0_ = (ch_) * KC;                                                              \
    size_t ao_ = (size_t)(m0 + crow) * lda + k0_ + cj * 8;                             \
    uint32_t d_ = (stb_) + OFF_AH + drow;                                              \
    cpa16(d_,      Ah + ao_,     16);                                                  \
    cpa16(d_ + 16, Ah + ao_ + 8, 16);                                                  \
    d_ = (stb_) + OFF_AL + drow;                                                       \
    cpa16(d_,      Al + ao_,     16);                                                  \
    cpa16(d_ + 16, Al + ao_ + 8, 16);                                                  \
    size_t bo_ = bvalid ? ((size_t)(n0 + crow) * ldb + k0_ + cj * 8) : 0;              \
    d_ = (stb_) + OFF_BH + drow;                                                       \
    cpa16(d_,      Bh + bo_,                 bvalid);                                  \
    cpa16(d_ + 16, Bh + bo_ + (bvalid ? 8:0), bvalid);                                 \
    d_ = (stb_) + OFF_BL + drow;                                                       \
    cpa16(d_,      Bl + bo_,                 bvalid);                                  \
    cpa16(d_ + 16, Bl + bo_ + (bvalid ? 8:0), bvalid);                                 \
} while (0)

    ISSUE(0, sb);
    CP_COMMIT();

    for (int ch = 0; ch < nch; ch++) {
        if (ch + 1 < nch) ISSUE(ch + 1, sb + ((ch + 1) & 1) * STAGE_B);
        CP_COMMIT();
        CP_WAIT1();
        __syncthreads();

        uint32_t base = sb + (ch & 1) * STAGE_B;
        uint32_t aHi = base + OFF_AH + 2u * (uint32_t)((wm * 64) * SP + a_loff);
        uint32_t aLo = base + OFF_AL + 2u * (uint32_t)((wm * 64) * SP + a_loff);
        uint32_t bHi = base + OFF_BH + 2u * (uint32_t)((wn * 32) * SP + b_loff);
        uint32_t bLo = base + OFF_BL + 2u * (uint32_t)((wn * 32) * SP + b_loff);

#pragma unroll
        for (int ks = 0; ks < 2; ks++) {
            uint32_t koff = (uint32_t)(ks * 32);
            uint32_t bh[2][4], bl[2][4], af[4][4];
#pragma unroll
            for (int jj = 0; jj < 2; jj++) {
                ldsm4(bh[jj], bHi + (uint32_t)(jj * 32 * SP) + koff);
                ldsm4(bl[jj], bLo + (uint32_t)(jj * 32 * SP) + koff);
            }
#pragma unroll
            for (int i = 0; i < 4; i++)
                ldsm4(af[i], aHi + (uint32_t)(i * 32 * SP) + koff);
#pragma unroll
            for (int i = 0; i < 4; i++)
#pragma unroll
                for (int j = 0; j < 4; j++) {
                    mma16816(acc[i][j], af[i], &bh[j >> 1][(j & 1) * 2]);
                    mma16816(acc[i][j], af[i], &bl[j >> 1][(j & 1) * 2]);
                }
#pragma unroll
            for (int i = 0; i < 4; i++)
                ldsm4(af[i], aLo + (uint32_t)(i * 32 * SP) + koff);
#pragma unroll
            for (int i = 0; i < 4; i++)
#pragma unroll
                for (int j = 0; j < 4; j++)
                    mma16816(acc[i][j], af[i], &bh[j >> 1][(j & 1) * 2]);
        }
        __syncthreads();
    }

    // ---- epilogue: regs -> smem staging -> coalesced writes ----
    {
        float* Cs = (float*)smem;
        int g = lane >> 2, t4 = lane & 3;
#pragma unroll
        for (int i = 0; i < 4; i++)
#pragma unroll
            for (int j = 0; j < 4; j++) {
                int r = wm * 64 + i * 16 + g;
                int c = wn * 32 + j * 8 + t4 * 2;
                *(float2*)&Cs[r * CS_LD + c]       = make_float2(acc[i][j][0], acc[i][j][1]);
                *(float2*)&Cs[(r + 8) * CS_LD + c] = make_float2(acc[i][j][2], acc[i][j][3]);
            }
    }
    __syncthreads();
    {
        const float* Cs = (const float*)smem;
        int c4 = lane << 2;
#pragma unroll
        for (int i = 0; i < 16; i++) {
            int r = i * 8 + wid;
            if (n0 + c4 < N) {
                float4 v = *(const float4*)&Cs[r * CS_LD + c4];
                v.x *= alpha; v.y *= alpha; v.z *= alpha; v.w *= alpha;
                if (bias) {
                    float4 bv = *(const float4*)(bias + n0 + c4);
                    v.x += bv.x; v.y += bv.y; v.z += bv.z; v.w += bv.w;
                }
                size_t off = (size_t)(m0 + r) * ldc + n0 + c4;
                if (Cf) *(float4*)(Cf + off) = v;
                if (Ch) {
                    uint64_t hv, lv; split4(v, hv, lv);
                    *(uint2*)(Ch + off) = make_uint2((uint32_t)hv, (uint32_t)(hv >> 32));
                    *(uint2*)(Cl + off) = make_uint2((uint32_t)lv, (uint32_t)(lv >> 32));
                }
            }
        }
    }
}

// ---------------- split kernels ----------------
__global__ void split_plain(const float4* __restrict__ src,
                            uint2* __restrict__ dh, uint2* __restrict__ dl, int n4)
{
    int i = blockIdx.x * blockDim.x + threadIdx.x;
    if (i < n4) {
        uint64_t h, l; split4(src[i], h, l);
        dh[i] = make_uint2((uint32_t)h, (uint32_t)(h >> 32));
        dl[i] = make_uint2((uint32_t)l, (uint32_t)(l >> 32));
    }
}

// kuw K-part [h][d][c] -> [h][c][d]
__global__ void split_trK(const float* __restrict__ src,
                          u16* __restrict__ dh, u16* __restrict__ dl)
{
    int i = blockIdx.x * blockDim.x + threadIdx.x;   // over H*KVRANK*QS
    int d = i & (QS_ - 1);
    int c = (i >> 7) & (KVRANK_ - 1);
    int h = i >> 16;
    float v = src[((size_t)h * QS_ + d) * KVRANK_ + c];
    split1(v, dh[i], dl[i]);
}

// ---------------- pointwise kernels ----------------
__device__ __forceinline__ float block_reduce_sum(float v, float* red) {
    int tid = threadIdx.x;
    for (int o = 16; o; o >>= 1) v += __shfl_xor_sync(0xffffffffu, v, o);
    if ((tid & 31) == 0) red[tid >> 5] = v;
    __syncthreads();
    if (tid < 32) {
        float w = (tid < (int)(blockDim.x >> 5)) ? red[tid] : 0.f;
        for (int o = 16; o; o >>= 1) w += __shfl_xor_sync(0xffffffffu, w, o);
        red[tid] = w;
    }
    __syncthreads();
    float r = red[0];
    __syncthreads();
    return r;
}

__global__ void rmsnorm_split_kernel(const float* __restrict__ in,
                                     u16* __restrict__ oh, u16* __restrict__ ol,
                                     const float* __restrict__ scale, int N)
{
    __shared__ float red[32];
    int r = blockIdx.x;
    const float* pi = in + (size_t)r * N;
    float ss = 0.f;
    for (int c = threadIdx.x; c < N; c += blockDim.x) { float v = pi[c]; ss += v * v; }
    ss = block_reduce_sum(ss, red);
    float inv = rsqrtf(ss / (float)N + 1e-6f);
    for (int c = threadIdx.x; c < N; c += blockDim.x) {
        float v = pi[c] * inv * scale[c];
        split1(v, oh[(size_t)r * N + c], ol[(size_t)r * N + c]);
    }
}

__device__ __forceinline__ void rope_angle(int s, int j, float* sn, float* cs) {
    int f = j & 31;
    float invf = 1.0f / powf(10000.0f, (float)(2 * f) / 64.0f);
    sincosf((float)s * invf, sn, cs);
}

__global__ void kv_post_kernel(const float* __restrict__ kvraw,
                               const float* __restrict__ kscale,
                               u16* __restrict__ kfh, u16* __restrict__ kfl,
                               u16* __restrict__ kfTh, u16* __restrict__ kfTl)
{
    __shared__ float red[32];
    int t = blockIdx.x;
    int b = t >> 10, s = t & (SEQ_ - 1);
    const float* pi = kvraw + (size_t)t * CD_;
    float ss = 0.f;
    for (int c = threadIdx.x; c < KVRANK_; c += blockDim.x) { float v = pi[c]; ss += v * v; }
    ss = block_reduce_sum(ss, red);
    float inv = rsqrtf(ss / (float)KVRANK_ + 1e-6f);
    for (int c = threadIdx.x; c < KVRANK_; c += blockDim.x) {
        float v = pi[c] * inv * kscale[c];
        u16 h, l; split1(v, h, l);
        kfh[(size_t)t * CD_ + c] = h;  kfl[(size_t)t * CD_ + c] = l;
        size_t to = ((size_t)b * KVRANK_ + c) * SEQ_ + s;
        kfTh[to] = h;  kfTl[to] = l;
    }
    if (threadIdx.x < ROT_) {
        int j = threadIdx.x;
        float sn, cs; rope_angle(s, j, &sn, &cs);
        float xv = pi[KVRANK_ + j];
        float hr = (j < 32) ? -pi[KVRANK_ + j + 32] : pi[KVRANK_ + j - 32];
        split1(xv * cs + hr * sn,
               kfh[(size_t)t * CD_ + KVRANK_ + j], kfl[(size_t)t * CD_ + KVRANK_ + j]);
    }
}

__global__ void q_post_kernel(const float* __restrict__ qfull,
                              u16* __restrict__ qah, u16* __restrict__ qal)
{
    int t = blockIdx.x;
    int h = threadIdx.x >> 6, j = threadIdx.x & 63;
    int b = t >> 10, s = t & (SEQ_ - 1);
    const float* src = qfull + (size_t)t * QUP_ + h * (QS_ + ROT_) + QS_;
    float xv = src[j];
    float hr = (j < 32) ? -src[j + 32] : src[j - 32];
    float sn, cs; rope_angle(s, j, &sn, &cs);
    size_t o = ((size_t)(b * H_ + h) * SEQ_ + s) * CD_ + KVRANK_ + j;
    split1(xv * cs + hr * sn, qah[o], qal[o]);
}

__global__ void softmax_kernel(const float* __restrict__ scores,
                               u16* __restrict__ Ph, u16* __restrict__ Pl)
{
    __shared__ float red[32];
    int s = blockIdx.x, bh = blockIdx.y;
    size_t base = ((size_t)bh * SEQ_ + s) * SEQ_;
    const float* row = scores + base;
    int L = s + 1;
    int tid = threadIdx.x;

    float m = -1e30f;
    for (int c = tid; c < L; c += blockDim.x) m = fmaxf(m, row[c]);
    for (int o = 16; o; o >>= 1) m = fmaxf(m, __shfl_xor_sync(0xffffffffu, m, o));
    if ((tid & 31) == 0) red[tid >> 5] = m;
    __syncthreads();
    if (tid < 32) {
        float w = (tid < (int)(blockDim.x >> 5)) ? red[tid] : -1e30f;
        for (int o = 16; o; o >>= 1) w = fmaxf(w, __shfl_xor_sync(0xffffffffu, w, o));
        red[tid] = w;
    }
    __syncthreads();
    m = red[0];
    __syncthreads();

    float sum = 0.f;
    for (int c = tid; c < L; c += blockDim.x) sum += expf(row[c] - m);
    sum = block_reduce_sum(sum, red);
    float inv = 1.f / sum;
    for (int c = tid; c < L; c += blockDim.x)
        split1(expf(row[c] - m) * inv, Ph[base + c], Pl[base + c]);

    int end = ((s >> 7) + 1) << 7;
    for (int c = L + tid; c < end; c += blockDim.x) { Ph[base + c] = 0; Pl[base + c] = 0; }
}

// ---------------- host side ----------------
static void launch_gemm(const u16* Ah, const u16* Al, const u16* Bh, const u16* Bl,
                        float* Cf, u16* Ch, u16* Cl, const float* bias,
                        int M, int N, int K, int lda, int ldb, int ldc,
                        long long sAo, long long sAi, long long sBo, long long sBi,
                        long long sCo, long long sCi, int zdiv, int nbatch,
                        float alpha, int causal, int klimit)
{
    dim3 grid((N + 127) / 128, M / 128, nbatch);
    gemm_bf<<<grid, 256, SMEM_TOTAL>>>(Ah, Al, Bh, Bl, Cf, Ch, Cl, bias,
                                       M, N, K, lda, ldb, ldc,
                                       sAo, sAi, sBo, sBi, sCo, sCi, zdiv,
                                       alpha, causal, klimit);
}

#define GETP(var, sym) cudaGetSymbolAddress((void**)&var, sym)

extern "C" void kernel_launch(void* const* d_in, const int* in_sizes, int n_in,
                              void* d_out, int out_size)
{
    const float* x   = (const float*)d_in[0];
    const float* qdw = (const float*)d_in[3];
    const float* qdb = (const float*)d_in[4];
    const float* qns = (const float*)d_in[5];
    const float* quw = (const float*)d_in[6];
    const float* qub = (const float*)d_in[7];
    const float* kdw = (const float*)d_in[8];
    const float* kdb = (const float*)d_in[9];
    const float* kns = (const float*)d_in[10];
    const float* kuw = (const float*)d_in[11];
    const float* ow  = (const float*)d_in[12];
    const float* ob  = (const float*)d_in[13];
    float* out = (float*)d_out;

    cudaFuncSetAttribute(gemm_bf, cudaFuncAttributeMaxDynamicSharedMemorySize, SMEM_TOTAL);

    float *qd, *kvraw, *qfull, *scr;
    GETP(qd, g_qd); GETP(kvraw, g_kvraw); GETP(qfull, g_qfull); GETP(scr, g_scr);

    u16 *xh,*xl,*qdwh,*qdwl,*quwh,*quwl,*kdwh,*kdwl,*owh,*owl,*kKTh,*kKTl,*kVh,*kVl;
    u16 *qnh,*qnl,*qfh,*qfl,*kfh,*kfl,*kfTh,*kfTl,*qah,*qal,*Ph,*Pl,*cch,*ccl,*cxh,*cxl;
    GETP(xh, s_xh); GETP(xl, s_xl);
    GETP(qdwh, s_qdwh); GETP(qdwl, s_qdwl);
    GETP(quwh, s_quwh); GETP(quwl, s_quwl);
    GETP(kdwh, s_kdwh); GETP(kdwl, s_kdwl);
    GETP(owh, s_owh);   GETP(owl, s_owl);
    GETP(kKTh, s_kKTh); GETP(kKTl, s_kKTl);
    GETP(kVh, s_kVh);   GETP(kVl, s_kVl);
    GETP(qnh, s_qnh);   GETP(qnl, s_qnl);
    GETP(qfh, s_qfh);   GETP(qfl, s_qfl);
    GETP(kfh, s_kfh);   GETP(kfl, s_kfl);
    GETP(kfTh, s_kfTh); GETP(kfTl, s_kfTl);
    GETP(qah, s_qah);   GETP(qal, s_qal);
    GETP(Ph, s_Ph);     GETP(Pl, s_Pl);
    GETP(cch, s_cch);   GETP(ccl, s_ccl);
    GETP(cxh, s_cxh);   GETP(cxl, s_cxl);

    const float inv_sqrt_d = 1.0f / sqrtf(192.0f);

    // ---- input splits ----
    auto spl = [](const float* s, u16* dh, u16* dl, size_t n) {
        int n4 = (int)(n / 4);
        split_plain<<<(n4 + 255) / 256, 256>>>((const float4*)s, (uint2*)dh, (uint2*)dl, n4);
    };
    spl(x,   xh,   xl,   (size_t)T_ * DIM_);
    spl(qdw, qdwh, qdwl, (size_t)QRANK_ * DIM_);
    spl(quw, quwh, quwl, (size_t)QUP_ * QRANK_);
    spl(kdw, kdwh, kdwl, (size_t)CD_ * DIM_);
    spl(ow,  owh,  owl,  (size_t)DIM_ * DIM_);
    spl(kuw + (size_t)H_ * QS_ * KVRANK_, kVh, kVl, (size_t)H_ * VD_ * KVRANK_);
    split_trK<<<(H_ * KVRANK_ * QS_) / 256, 256>>>(kuw, kKTh, kKTl);

    // 1) q_down -> fp32
    launch_gemm(xh, xl, qdwh, qdwl, qd, nullptr, nullptr, qdb,
                T_, QRANK_, DIM_, DIM_, DIM_, QRANK_,
                0, 0, 0, 0, 0, 0, 1, 1, 1.f, 0, 0);
    rmsnorm_split_kernel<<<T_, 256>>>(qd, qnh, qnl, qns, QRANK_);

    // 2) q_up -> fp32 (for rope) + hi/lo (for absorb)
    launch_gemm(qnh, qnl, quwh, quwl, qfull, qfh, qfl, qub,
                T_, QUP_, QRANK_, QRANK_, QRANK_, QUP_,
                0, 0, 0, 0, 0, 0, 1, 1, 1.f, 0, 0);

    // 3) kv_down -> fp32
    launch_gemm(xh, xl, kdwh, kdwl, kvraw, nullptr, nullptr, kdb,
                T_, CD_, DIM_, DIM_, DIM_, CD_,
                0, 0, 0, 0, 0, 0, 1, 1, 1.f, 0, 0);
    kv_post_kernel<<<T_, 256>>>(kvraw, kns, kfh, kfl, kfTh, kfTl);
    q_post_kernel<<<T_, 1024>>>(qfull, qah, qal);

    // 4) absorbed q: per (b,h) q_static[1024,128] @ w_kT[512,128]^T -> qall[...,0:512]
    launch_gemm(qfh, qfl, kKTh, kKTl, nullptr, qah, qal, nullptr,
                SEQ_, KVRANK_, QS_, QUP_, QS_, CD_,
                (long long)SEQ_ * QUP_, (long long)(QS_ + ROT_),
                0, (long long)KVRANK_ * QS_,
                (long long)H_ * SEQ_ * CD_, (long long)SEQ_ * CD_,
                H_, BS_ * H_, 1.f, 0, 0);

    // 5) scores: Q[1024,576] @ K[1024,576]^T / sqrt(192), causal
    launch_gemm(qah, qal, kfh, kfl, scr, nullptr, nullptr, nullptr,
                SEQ_, SEQ_, CD_, CD_, CD_, SEQ_,
                (long long)H_ * SEQ_ * CD_, (long long)SEQ_ * CD_,
                (long long)SEQ_ * CD_, 0,
                (long long)H_ * SEQ_ * SEQ_, (long long)SEQ_ * SEQ_,
                H_, BS_ * H_, inv_sqrt_d, 1, 0);

    softmax_kernel<<<dim3(SEQ_, BS_ * H_), 256>>>(scr, Ph, Pl);

    // 6) ctx_c: P[1024,1024] @ kvT[512,1024]^T (klimit)
    launch_gemm(Ph, Pl, kfTh, kfTl, nullptr, cch, ccl, nullptr,
                SEQ_, KVRANK_, SEQ_, SEQ_, SEQ_, KVRANK_,
                (long long)H_ * SEQ_ * SEQ_, (long long)SEQ_ * SEQ_,
                (long long)KVRANK_ * SEQ_, 0,
                (long long)H_ * SEQ_ * KVRANK_, (long long)SEQ_ * KVRANK_,
                H_, BS_ * H_, 1.f, 0, 1);

    // 7) v-proj: ctx_c[1024,512] @ w_v[128,512]^T -> ctx[b*S+s][h*128+d]
    launch_gemm(cch, ccl, kVh, kVl, nullptr, cxh, cxl, nullptr,
                SEQ_, VD_, KVRANK_, KVRANK_, KVRANK_, DIM_,
                (long long)H_ * SEQ_ * KVRANK_, (long long)SEQ_ * KVRANK_,
                0, (long long)VD_ * KVRANK_,
                (long long)SEQ_ * DIM_, (long long)VD_,
                H_, BS_ * H_, 1.f, 0, 0);

    // 8) out
    launch_gemm(cxh, cxl, owh, owl, out, nullptr, nullptr, ob,
                T_, DIM_, DIM_, DIM_, DIM_, DIM_,
                0, 0, 0, 0, 0, 0, 1, 1, 1.f, 0, 0);
}